// round 2
// baseline (speedup 1.0000x reference)
#include <cuda_runtime.h>

// Problem constants (fixed by the reference).
#define BATCH 512
#define LSEQ  24576
#define LP    8192        // LSEQ / 3
#define HID   10

// Scratch for conv output (16 MB + pad for the prefetch overread).
__device__ float g_conv[(size_t)BATCH * LP + 4];

// ---------------------------------------------------------------------------
// Kernel 1: conv1d k=3 stride=3 + bias + relu.  Each thread produces 4 outputs
// from 3 float4 loads (12 contiguous inputs).
// ---------------------------------------------------------------------------
__global__ void conv_kernel(const float* __restrict__ x,
                            const float* __restrict__ cw,
                            const float* __restrict__ cb) {
    int idx = blockIdx.x * blockDim.x + threadIdx.x;   // 0 .. 512*2048-1
    int b = idx >> 11;          // 2048 quads per batch row
    int i = idx & 2047;
    if (b >= BATCH) return;

    const float4* xp = reinterpret_cast<const float4*>(x + (size_t)b * LSEQ + 12 * i);
    float4 a = xp[0];
    float4 m = xp[1];
    float4 c = xp[2];

    float w0 = cw[0], w1 = cw[1], w2 = cw[2], b0 = cb[0];

    float o0 = fmaf(a.x, w0, fmaf(a.y, w1, fmaf(a.z, w2, b0)));
    float o1 = fmaf(a.w, w0, fmaf(m.x, w1, fmaf(m.y, w2, b0)));
    float o2 = fmaf(m.z, w0, fmaf(m.w, w1, fmaf(c.x, w2, b0)));
    float o3 = fmaf(c.y, w0, fmaf(c.z, w1, fmaf(c.w, w2, b0)));

    float4 o;
    o.x = fmaxf(o0, 0.0f);
    o.y = fmaxf(o1, 0.0f);
    o.z = fmaxf(o2, 0.0f);
    o.w = fmaxf(o3, 0.0f);
    *reinterpret_cast<float4*>(g_conv + (size_t)b * LP + 4 * i) = o;
}

// ---------------------------------------------------------------------------
// f32x2 packed helpers (sm_103a: fma.rn.f32x2 -> single FFMA2).
// ---------------------------------------------------------------------------
typedef unsigned long long u64;

__device__ __forceinline__ u64 dup2(float x) {
    u64 r;
    asm("mov.b64 %0, {%1, %1};" : "=l"(r) : "f"(x));
    return r;
}
__device__ __forceinline__ u64 pack2(float lo, float hi) {
    u64 r;
    asm("mov.b64 %0, {%1, %2};" : "=l"(r) : "f"(lo), "f"(hi));
    return r;
}
__device__ __forceinline__ u64 ffma2(u64 a, u64 b, u64 c) {
    u64 d;
    asm("fma.rn.f32x2 %0, %1, %2, %3;" : "=l"(d) : "l"(a), "l"(b), "l"(c));
    return d;
}
__device__ __forceinline__ u64 add2f(u64 a, u64 b) {
    u64 d;
    asm("add.rn.f32x2 %0, %1, %2;" : "=l"(d) : "l"(a), "l"(b));
    return d;
}
__device__ __forceinline__ void unpack2(u64 v, float& lo, float& hi) {
    asm("mov.b64 {%0, %1}, %2;" : "=f"(lo), "=f"(hi) : "l"(v));
}

// ---------------------------------------------------------------------------
// HW tanh (MUFU.TANH): 1 MUFU op, 16-cyc latency.
// ---------------------------------------------------------------------------
__device__ __forceinline__ float tanh_apx(float x) {
    float y;
    asm("tanh.approx.f32 %0, %1;" : "=f"(y) : "f"(x));
    return y;
}
__device__ __forceinline__ float sigm_apx(float x) {
    return fmaf(tanh_apx(0.5f * x), 0.5f, 0.5f);
}

// ---------------------------------------------------------------------------
// Kernel 2: LSTM scan + final MLP.
// One batch element per 16-lane warp segment; lane j<10 owns hidden unit j.
// Gates paired (i,f) and (g,o); recurrent dot via FFMA2 in two 5-deep chains.
// ---------------------------------------------------------------------------
__global__ void __launch_bounds__(64, 1)
lstm_kernel(const float* __restrict__ w_ih,
            const float* __restrict__ w_hh,
            const float* __restrict__ b_ih,
            const float* __restrict__ b_hh,
            const float* __restrict__ mlp_w,
            const float* __restrict__ mlp_b,
            float* __restrict__ out) {
    int tid = blockIdx.x * blockDim.x + threadIdx.x;
    int grp = tid >> 4;                 // batch element, 0..511
    int j   = tid & 15;                 // lane within segment
    int jc  = j < HID ? j : HID - 1;    // clamp idle lanes onto valid rows
    if (grp >= BATCH) return;

    // Packed recurrent weights: (i,f) pair and (g,o) pair per k.
    u64 wif2[HID], wgo2[HID];
#pragma unroll
    for (int k = 0; k < HID; k++) {
        wif2[k] = pack2(w_hh[(0 * HID + jc) * HID + k],
                        w_hh[(1 * HID + jc) * HID + k]);
        wgo2[k] = pack2(w_hh[(2 * HID + jc) * HID + k],
                        w_hh[(3 * HID + jc) * HID + k]);
    }
    u64 wx_if = pack2(w_ih[0 * HID + jc], w_ih[1 * HID + jc]);
    u64 wx_go = pack2(w_ih[2 * HID + jc], w_ih[3 * HID + jc]);
    u64 bb_if = pack2(b_ih[0 * HID + jc] + b_hh[0 * HID + jc],
                      b_ih[1 * HID + jc] + b_hh[1 * HID + jc]);
    u64 bb_go = pack2(b_ih[2 * HID + jc] + b_hh[2 * HID + jc],
                      b_ih[3 * HID + jc] + b_hh[3 * HID + jc]);

    float h = 0.0f, cst = 0.0f;

    const float* convp = g_conv + (size_t)grp * LP;
    float4 cur = *reinterpret_cast<const float4*>(convp);

    for (int t4 = 0; t4 < LP / 4; t4++) {
        // Prefetch next quad (padded overread on the last iteration).
        float4 nxt = *reinterpret_cast<const float4*>(convp + 4 * t4 + 4);

        float cts[4] = {cur.x, cur.y, cur.z, cur.w};
#pragma unroll
        for (int u = 0; u < 4; u++) {
            u64 ct2 = dup2(cts[u]);
            // chain 0: k = 0..4 (starts from input + bias)
            u64 accA0 = ffma2(wx_if, ct2, bb_if);
            u64 accB0 = ffma2(wx_go, ct2, bb_go);
            // chain 1: k = 5..9 (starts from zero)
            u64 accA1 = 0ull, accB1 = 0ull;
#pragma unroll
            for (int k = 0; k < 5; k++) {
                float hk = __shfl_sync(0xffffffffu, h, k, 16);
                u64 hk2 = dup2(hk);
                accA0 = ffma2(wif2[k], hk2, accA0);
                accB0 = ffma2(wgo2[k], hk2, accB0);
            }
#pragma unroll
            for (int k = 5; k < HID; k++) {
                float hk = __shfl_sync(0xffffffffu, h, k, 16);
                u64 hk2 = dup2(hk);
                accA1 = ffma2(wif2[k], hk2, accA1);
                accB1 = ffma2(wgo2[k], hk2, accB1);
            }
            u64 accA = add2f(accA0, accA1);
            u64 accB = add2f(accB0, accB1);

            float ai, af, ag, ao;
            unpack2(accA, ai, af);
            unpack2(accB, ag, ao);

            float ig = sigm_apx(ai);
            float fg = sigm_apx(af);
            float og = sigm_apx(ao);
            float gg = tanh_apx(ag);

            cst = fmaf(fg, cst, ig * gg);
            h = og * tanh_apx(cst);
        }
        cur = nxt;
    }

    // Final MLP: gather h_0..h_9, lanes 0..2 emit the 3 outputs.
    float hv[HID];
#pragma unroll
    for (int k = 0; k < HID; k++)
        hv[k] = __shfl_sync(0xffffffffu, h, k, 16);

    if (j < 3) {
        float acc = mlp_b[j];
#pragma unroll
        for (int k = 0; k < HID; k++)
            acc = fmaf(mlp_w[j * HID + k], hv[k], acc);
        out[grp * 3 + j] = acc;
    }
}

// ---------------------------------------------------------------------------
extern "C" void kernel_launch(void* const* d_in, const int* in_sizes, int n_in,
                              void* d_out, int out_size) {
    const float* x      = (const float*)d_in[0];
    const float* conv_w = (const float*)d_in[1];
    const float* conv_b = (const float*)d_in[2];
    const float* w_ih   = (const float*)d_in[3];
    const float* w_hh   = (const float*)d_in[4];
    const float* b_ih   = (const float*)d_in[5];
    const float* b_hh   = (const float*)d_in[6];
    const float* mlp_w  = (const float*)d_in[7];
    const float* mlp_b  = (const float*)d_in[8];
    float* out = (float*)d_out;

    // Conv: 512*2048 threads, 4 outputs each.
    {
        int total = BATCH * (LP / 4);
        int threads = 256;
        int blocks = (total + threads - 1) / threads;
        conv_kernel<<<blocks, threads>>>(x, conv_w, conv_b);
    }
    // LSTM: 512 groups * 16 lanes = 8192 threads, 64-thread blocks to spread
    // across ~128 SMs at 1 warp/SMSP.
    {
        int threads = 64;
        int blocks = (BATCH * 16) / threads;   // 128
        lstm_kernel<<<blocks, threads>>>(w_ih, w_hh, b_ih, b_hh, mlp_w, mlp_b, out);
    }
}

// round 3
// speedup vs baseline: 1.7357x; 1.7357x over previous
#include <cuda_runtime.h>

// Problem constants (fixed by the reference).
#define BATCH 512
#define LSEQ  24576
#define LP    8192        // LSEQ / 3
#define HID   10

// Scratch for conv output (16 MB + pad for the prefetch overread).
__device__ float g_conv[(size_t)BATCH * LP + 4];

// ---------------------------------------------------------------------------
// Kernel 1: conv1d k=3 stride=3 + bias + relu.  Each thread produces 4 outputs
// from 3 float4 loads (12 contiguous inputs).
// ---------------------------------------------------------------------------
__global__ void conv_kernel(const float* __restrict__ x,
                            const float* __restrict__ cw,
                            const float* __restrict__ cb) {
    int idx = blockIdx.x * blockDim.x + threadIdx.x;   // 0 .. 512*2048-1
    int b = idx >> 11;          // 2048 quads per batch row
    int i = idx & 2047;
    if (b >= BATCH) return;

    const float4* xp = reinterpret_cast<const float4*>(x + (size_t)b * LSEQ + 12 * i);
    float4 a = xp[0];
    float4 m = xp[1];
    float4 c = xp[2];

    float w0 = cw[0], w1 = cw[1], w2 = cw[2], b0 = cb[0];

    float o0 = fmaf(a.x, w0, fmaf(a.y, w1, fmaf(a.z, w2, b0)));
    float o1 = fmaf(a.w, w0, fmaf(m.x, w1, fmaf(m.y, w2, b0)));
    float o2 = fmaf(m.z, w0, fmaf(m.w, w1, fmaf(c.x, w2, b0)));
    float o3 = fmaf(c.y, w0, fmaf(c.z, w1, fmaf(c.w, w2, b0)));

    float4 o;
    o.x = fmaxf(o0, 0.0f);
    o.y = fmaxf(o1, 0.0f);
    o.z = fmaxf(o2, 0.0f);
    o.w = fmaxf(o3, 0.0f);
    *reinterpret_cast<float4*>(g_conv + (size_t)b * LP + 4 * i) = o;
}

// ---------------------------------------------------------------------------
// HW tanh (MUFU.TANH): 1 MUFU op, 16-cyc latency.
// ---------------------------------------------------------------------------
__device__ __forceinline__ float tanh_apx(float x) {
    float y;
    asm("tanh.approx.f32 %0, %1;" : "=f"(y) : "f"(x));
    return y;
}

// ---------------------------------------------------------------------------
// Kernel 2: LSTM scan + final MLP.
// One batch element per 16-lane warp segment; lane j<10 owns hidden unit j.
// Scalar FFMA, each gate dot split into two 5-deep chains (+1 add).
// i/f/o weights and biases pre-scaled by 0.5 so sigmoid(x) = fma(tanh(acc),.5,.5)
// with no pre-scale multiply on the critical path.
// ---------------------------------------------------------------------------
__global__ void __launch_bounds__(128, 1)
lstm_kernel(const float* __restrict__ w_ih,
            const float* __restrict__ w_hh,
            const float* __restrict__ b_ih,
            const float* __restrict__ b_hh,
            const float* __restrict__ mlp_w,
            const float* __restrict__ mlp_b,
            float* __restrict__ out) {
    int tid = blockIdx.x * blockDim.x + threadIdx.x;
    int grp = tid >> 4;                 // batch element, 0..511
    int j   = tid & 15;                 // lane within segment
    int jc  = j < HID ? j : HID - 1;    // clamp idle lanes onto valid rows
    if (grp >= BATCH) return;

    // Recurrent weights (torch gate order i,f,g,o). Sigmoid gates scaled 0.5.
    float wi[HID], wf[HID], wg[HID], wo[HID];
#pragma unroll
    for (int k = 0; k < HID; k++) {
        wi[k] = 0.5f * w_hh[(0 * HID + jc) * HID + k];
        wf[k] = 0.5f * w_hh[(1 * HID + jc) * HID + k];
        wg[k] =        w_hh[(2 * HID + jc) * HID + k];
        wo[k] = 0.5f * w_hh[(3 * HID + jc) * HID + k];
    }
    float wxi = 0.5f * w_ih[0 * HID + jc];
    float wxf = 0.5f * w_ih[1 * HID + jc];
    float wxg =        w_ih[2 * HID + jc];
    float wxo = 0.5f * w_ih[3 * HID + jc];
    float bbi = 0.5f * (b_ih[0 * HID + jc] + b_hh[0 * HID + jc]);
    float bbf = 0.5f * (b_ih[1 * HID + jc] + b_hh[1 * HID + jc]);
    float bbg =        (b_ih[2 * HID + jc] + b_hh[2 * HID + jc]);
    float bbo = 0.5f * (b_ih[3 * HID + jc] + b_hh[3 * HID + jc]);

    float h = 0.0f, cst = 0.0f;

    const float* convp = g_conv + (size_t)grp * LP;
    float4 cur = *reinterpret_cast<const float4*>(convp);

    for (int t4 = 0; t4 < LP / 4; t4++) {
        // Prefetch next quad (padded overread on the last iteration).
        float4 nxt = *reinterpret_cast<const float4*>(convp + 4 * t4 + 4);

        float cts[4] = {cur.x, cur.y, cur.z, cur.w};
#pragma unroll
        for (int u = 0; u < 4; u++) {
            float ct = cts[u];
            // chain 0 (k=0..4) seeded with input+bias; chain 1 (k=5..9) from 0.
            float ai0 = fmaf(wxi, ct, bbi), ai1 = 0.0f;
            float af0 = fmaf(wxf, ct, bbf), af1 = 0.0f;
            float ag0 = fmaf(wxg, ct, bbg), ag1 = 0.0f;
            float ao0 = fmaf(wxo, ct, bbo), ao1 = 0.0f;
#pragma unroll
            for (int k = 0; k < 5; k++) {
                float hk = __shfl_sync(0xffffffffu, h, k, 16);
                ai0 = fmaf(wi[k], hk, ai0);
                af0 = fmaf(wf[k], hk, af0);
                ag0 = fmaf(wg[k], hk, ag0);
                ao0 = fmaf(wo[k], hk, ao0);
            }
#pragma unroll
            for (int k = 5; k < HID; k++) {
                float hk = __shfl_sync(0xffffffffu, h, k, 16);
                ai1 = fmaf(wi[k], hk, ai1);
                af1 = fmaf(wf[k], hk, af1);
                ag1 = fmaf(wg[k], hk, ag1);
                ao1 = fmaf(wo[k], hk, ao1);
            }
            // Sigmoid gates: acc already holds 0.5*preact.
            float ig = fmaf(tanh_apx(ai0 + ai1), 0.5f, 0.5f);
            float fg = fmaf(tanh_apx(af0 + af1), 0.5f, 0.5f);
            float og = fmaf(tanh_apx(ao0 + ao1), 0.5f, 0.5f);
            float gg = tanh_apx(ag0 + ag1);

            cst = fmaf(fg, cst, ig * gg);
            h = og * tanh_apx(cst);
        }
        cur = nxt;
    }

    // Final MLP: gather h_0..h_9, lanes 0..2 emit the 3 outputs.
    float hv[HID];
#pragma unroll
    for (int k = 0; k < HID; k++)
        hv[k] = __shfl_sync(0xffffffffu, h, k, 16);

    if (j < 3) {
        float acc = mlp_b[j];
#pragma unroll
        for (int k = 0; k < HID; k++)
            acc = fmaf(mlp_w[j * HID + k], hv[k], acc);
        out[grp * 3 + j] = acc;
    }
}

// ---------------------------------------------------------------------------
extern "C" void kernel_launch(void* const* d_in, const int* in_sizes, int n_in,
                              void* d_out, int out_size) {
    const float* x      = (const float*)d_in[0];
    const float* conv_w = (const float*)d_in[1];
    const float* conv_b = (const float*)d_in[2];
    const float* w_ih   = (const float*)d_in[3];
    const float* w_hh   = (const float*)d_in[4];
    const float* b_ih   = (const float*)d_in[5];
    const float* b_hh   = (const float*)d_in[6];
    const float* mlp_w  = (const float*)d_in[7];
    const float* mlp_b  = (const float*)d_in[8];
    float* out = (float*)d_out;

    // Conv: 512*2048 threads, 4 outputs each.
    {
        int total = BATCH * (LP / 4);
        int threads = 256;
        int blocks = (total + threads - 1) / threads;
        conv_kernel<<<blocks, threads>>>(x, conv_w, conv_b);
    }
    // LSTM: 512 groups * 16 lanes = 8192 threads (R1 config: 64 blocks x 128).
    {
        int threads = 128;
        int blocks = (BATCH * 16) / threads;   // 64
        lstm_kernel<<<blocks, threads>>>(w_ih, w_hh, b_ih, b_hh, mlp_w, mlp_b, out);
    }
}

// round 4
// speedup vs baseline: 1.8080x; 1.0417x over previous
#include <cuda_runtime.h>

// Problem constants (fixed by the reference).
#define BATCH 512
#define LSEQ  24576
#define LP    8192        // LSEQ / 3
#define HID   10

// Scratch for conv output (16 MB + pad for the prefetch overread).
__device__ float g_conv[(size_t)BATCH * LP + 4];

// ---------------------------------------------------------------------------
// Kernel 1: conv1d k=3 stride=3 + bias + relu.
// ---------------------------------------------------------------------------
__global__ void conv_kernel(const float* __restrict__ x,
                            const float* __restrict__ cw,
                            const float* __restrict__ cb) {
    int idx = blockIdx.x * blockDim.x + threadIdx.x;   // 0 .. 512*2048-1
    int b = idx >> 11;          // 2048 quads per batch row
    int i = idx & 2047;
    if (b >= BATCH) return;

    const float4* xp = reinterpret_cast<const float4*>(x + (size_t)b * LSEQ + 12 * i);
    float4 a = xp[0];
    float4 m = xp[1];
    float4 c = xp[2];

    float w0 = cw[0], w1 = cw[1], w2 = cw[2], b0 = cb[0];

    float o0 = fmaf(a.x, w0, fmaf(a.y, w1, fmaf(a.z, w2, b0)));
    float o1 = fmaf(a.w, w0, fmaf(m.x, w1, fmaf(m.y, w2, b0)));
    float o2 = fmaf(m.z, w0, fmaf(m.w, w1, fmaf(c.x, w2, b0)));
    float o3 = fmaf(c.y, w0, fmaf(c.z, w1, fmaf(c.w, w2, b0)));

    float4 o;
    o.x = fmaxf(o0, 0.0f);
    o.y = fmaxf(o1, 0.0f);
    o.z = fmaxf(o2, 0.0f);
    o.w = fmaxf(o3, 0.0f);
    *reinterpret_cast<float4*>(g_conv + (size_t)b * LP + 4 * i) = o;
}

// ---------------------------------------------------------------------------
// HW tanh (MUFU.TANH): 1 MUFU op, 16-cyc latency.
// ---------------------------------------------------------------------------
__device__ __forceinline__ float tanh_apx(float x) {
    float y;
    asm("tanh.approx.f32 %0, %1;" : "=f"(y) : "f"(x));
    return y;
}

// Shared-memory h broadcast helpers (32-bit smem addresses, volatile asm to
// pin STS-before-LDS program order; same-warp smem ops complete in order).
__device__ __forceinline__ void sts_f32(unsigned addr, float v) {
    asm volatile("st.shared.f32 [%0], %1;" :: "r"(addr), "f"(v) : "memory");
}
__device__ __forceinline__ void lds_v4(unsigned addr, float& a, float& b,
                                       float& c, float& d) {
    asm volatile("ld.shared.v4.f32 {%0,%1,%2,%3}, [%4];"
                 : "=f"(a), "=f"(b), "=f"(c), "=f"(d) : "r"(addr) : "memory");
}
__device__ __forceinline__ void lds_v2(unsigned addr, float& a, float& b) {
    asm volatile("ld.shared.v2.f32 {%0,%1}, [%2];"
                 : "=f"(a), "=f"(b) : "r"(addr) : "memory");
}

// ---------------------------------------------------------------------------
// Kernel 2: LSTM scan + final MLP.
// One batch element per 16-lane warp segment; lane j<10 owns hidden unit j.
// h broadcast via smem: 1 STS + (LDS.128 x2 + LDS.64) instead of 10 SHFLs.
// i/f/o weights and biases pre-scaled by 0.5 so sigmoid(x)=fma(tanh(acc),.5,.5).
// ---------------------------------------------------------------------------
__global__ void __launch_bounds__(128, 1)
lstm_kernel(const float* __restrict__ w_ih,
            const float* __restrict__ w_hh,
            const float* __restrict__ b_ih,
            const float* __restrict__ b_hh,
            const float* __restrict__ mlp_w,
            const float* __restrict__ mlp_b,
            float* __restrict__ out) {
    __shared__ float hbuf[8 * 16];      // 8 segments/block * 16 slots

    int tid = blockIdx.x * blockDim.x + threadIdx.x;
    int grp = tid >> 4;                 // batch element, 0..511
    int j   = tid & 15;                 // lane within segment
    int jc  = j < HID ? j : HID - 1;    // clamp idle lanes onto valid rows
    if (grp >= BATCH) return;

    int seg = (threadIdx.x >> 4);       // segment within block, 0..7
    unsigned sbase = (unsigned)__cvta_generic_to_shared(&hbuf[seg * 16]);
    unsigned smy   = sbase + 4u * (unsigned)j;

    // Recurrent weights (torch gate order i,f,g,o). Sigmoid gates scaled 0.5.
    float wi[HID], wf[HID], wg[HID], wo[HID];
#pragma unroll
    for (int k = 0; k < HID; k++) {
        wi[k] = 0.5f * w_hh[(0 * HID + jc) * HID + k];
        wf[k] = 0.5f * w_hh[(1 * HID + jc) * HID + k];
        wg[k] =        w_hh[(2 * HID + jc) * HID + k];
        wo[k] = 0.5f * w_hh[(3 * HID + jc) * HID + k];
    }
    float wxi = 0.5f * w_ih[0 * HID + jc];
    float wxf = 0.5f * w_ih[1 * HID + jc];
    float wxg =        w_ih[2 * HID + jc];
    float wxo = 0.5f * w_ih[3 * HID + jc];
    float bbi = 0.5f * (b_ih[0 * HID + jc] + b_hh[0 * HID + jc]);
    float bbf = 0.5f * (b_ih[1 * HID + jc] + b_hh[1 * HID + jc]);
    float bbg =        (b_ih[2 * HID + jc] + b_hh[2 * HID + jc]);
    float bbo = 0.5f * (b_ih[3 * HID + jc] + b_hh[3 * HID + jc]);

    float cst = 0.0f;

    // Seed h = 0 in smem.
    sts_f32(smy, 0.0f);

    const float* convp = g_conv + (size_t)grp * LP;
    float4 cur = *reinterpret_cast<const float4*>(convp);

    for (int t4 = 0; t4 < LP / 4; t4++) {
        // Prefetch next quad (padded overread on the last iteration).
        float4 nxt = *reinterpret_cast<const float4*>(convp + 4 * t4 + 4);

        float cts[4] = {cur.x, cur.y, cur.z, cur.w};
#pragma unroll
        for (int u = 0; u < 4; u++) {
            float ct = cts[u];
            // Broadcast previous h: 3 vector LDS (all lanes of a segment read
            // the same addresses -> smem broadcast, conflict-free).
            float h0, h1, h2, h3, h4, h5, h6, h7, h8, h9;
            lds_v4(sbase,       h0, h1, h2, h3);
            lds_v4(sbase + 16u, h4, h5, h6, h7);
            lds_v2(sbase + 32u, h8, h9);

            // chain 0 (k=0..4) seeded with input+bias; chain 1 (k=5..9) from 0.
            float ai0 = fmaf(wxi, ct, bbi);
            float af0 = fmaf(wxf, ct, bbf);
            float ag0 = fmaf(wxg, ct, bbg);
            float ao0 = fmaf(wxo, ct, bbo);

            ag0 = fmaf(wg[0], h0, ag0);
            ai0 = fmaf(wi[0], h0, ai0);
            af0 = fmaf(wf[0], h0, af0);
            ao0 = fmaf(wo[0], h0, ao0);
            ag0 = fmaf(wg[1], h1, ag0);
            ai0 = fmaf(wi[1], h1, ai0);
            af0 = fmaf(wf[1], h1, af0);
            ao0 = fmaf(wo[1], h1, ao0);
            ag0 = fmaf(wg[2], h2, ag0);
            ai0 = fmaf(wi[2], h2, ai0);
            af0 = fmaf(wf[2], h2, af0);
            ao0 = fmaf(wo[2], h2, ao0);
            ag0 = fmaf(wg[3], h3, ag0);
            ai0 = fmaf(wi[3], h3, ai0);
            af0 = fmaf(wf[3], h3, af0);
            ao0 = fmaf(wo[3], h3, ao0);
            ag0 = fmaf(wg[4], h4, ag0);
            ai0 = fmaf(wi[4], h4, ai0);
            af0 = fmaf(wf[4], h4, af0);
            ao0 = fmaf(wo[4], h4, ao0);

            float ag1 = wg[5] * h5;
            float ai1 = wi[5] * h5;
            float af1 = wf[5] * h5;
            float ao1 = wo[5] * h5;
            ag1 = fmaf(wg[6], h6, ag1);
            ai1 = fmaf(wi[6], h6, ai1);
            af1 = fmaf(wf[6], h6, af1);
            ao1 = fmaf(wo[6], h6, ao1);
            ag1 = fmaf(wg[7], h7, ag1);
            ai1 = fmaf(wi[7], h7, ai1);
            af1 = fmaf(wf[7], h7, af1);
            ao1 = fmaf(wo[7], h7, ao1);
            ag1 = fmaf(wg[8], h8, ag1);
            ai1 = fmaf(wi[8], h8, ai1);
            af1 = fmaf(wf[8], h8, af1);
            ao1 = fmaf(wo[8], h8, ao1);
            ag1 = fmaf(wg[9], h9, ag1);
            ai1 = fmaf(wi[9], h9, ai1);
            af1 = fmaf(wf[9], h9, af1);
            ao1 = fmaf(wo[9], h9, ao1);

            // Activations in consumption order: g, i, f first (feed c), o last.
            float gg = tanh_apx(ag0 + ag1);
            float ig = fmaf(tanh_apx(ai0 + ai1), 0.5f, 0.5f);
            float fg = fmaf(tanh_apx(af0 + af1), 0.5f, 0.5f);
            float og = fmaf(tanh_apx(ao0 + ao1), 0.5f, 0.5f);

            cst = fmaf(fg, cst, ig * gg);
            float h = og * tanh_apx(cst);

            // Publish new h for the next step.
            sts_f32(smy, h);
        }
        cur = nxt;
    }

    // Final MLP: read h_0..h_9 from smem; lanes 0..2 emit the 3 outputs.
    if (j < 3) {
        float h0, h1, h2, h3, h4, h5, h6, h7, h8, h9;
        lds_v4(sbase,       h0, h1, h2, h3);
        lds_v4(sbase + 16u, h4, h5, h6, h7);
        lds_v2(sbase + 32u, h8, h9);
        const float* mw = mlp_w + j * HID;
        float acc = mlp_b[j];
        acc = fmaf(mw[0], h0, acc);
        acc = fmaf(mw[1], h1, acc);
        acc = fmaf(mw[2], h2, acc);
        acc = fmaf(mw[3], h3, acc);
        acc = fmaf(mw[4], h4, acc);
        acc = fmaf(mw[5], h5, acc);
        acc = fmaf(mw[6], h6, acc);
        acc = fmaf(mw[7], h7, acc);
        acc = fmaf(mw[8], h8, acc);
        acc = fmaf(mw[9], h9, acc);
        out[grp * 3 + j] = acc;
    }
}

// ---------------------------------------------------------------------------
extern "C" void kernel_launch(void* const* d_in, const int* in_sizes, int n_in,
                              void* d_out, int out_size) {
    const float* x      = (const float*)d_in[0];
    const float* conv_w = (const float*)d_in[1];
    const float* conv_b = (const float*)d_in[2];
    const float* w_ih   = (const float*)d_in[3];
    const float* w_hh   = (const float*)d_in[4];
    const float* b_ih   = (const float*)d_in[5];
    const float* b_hh   = (const float*)d_in[6];
    const float* mlp_w  = (const float*)d_in[7];
    const float* mlp_b  = (const float*)d_in[8];
    float* out = (float*)d_out;

    // Conv: 512*2048 threads, 4 outputs each.
    {
        int total = BATCH * (LP / 4);
        int threads = 256;
        int blocks = (total + threads - 1) / threads;
        conv_kernel<<<blocks, threads>>>(x, conv_w, conv_b);
    }
    // LSTM: 512 groups * 16 lanes = 8192 threads (64 blocks x 128).
    {
        int threads = 128;
        int blocks = (BATCH * 16) / threads;   // 64
        lstm_kernel<<<blocks, threads>>>(w_ih, w_hh, b_ih, b_hh, mlp_w, mlp_b, out);
    }
}

// round 5
// speedup vs baseline: 1.9737x; 1.0917x over previous
#include <cuda_runtime.h>

// Problem constants (fixed by the reference).
#define BATCH 512
#define LSEQ  24576
#define LP    8192        // LSEQ / 3
#define HID   10

// Scratch for conv output (16 MB + pad for the prefetch overread).
__device__ float g_conv[(size_t)BATCH * LP + 4];

// ---------------------------------------------------------------------------
// Kernel 1: conv1d k=3 stride=3 + bias + relu.
// ---------------------------------------------------------------------------
__global__ void conv_kernel(const float* __restrict__ x,
                            const float* __restrict__ cw,
                            const float* __restrict__ cb) {
    int idx = blockIdx.x * blockDim.x + threadIdx.x;   // 0 .. 512*2048-1
    int b = idx >> 11;          // 2048 quads per batch row
    int i = idx & 2047;
    if (b >= BATCH) return;

    const float4* xp = reinterpret_cast<const float4*>(x + (size_t)b * LSEQ + 12 * i);
    float4 a = xp[0];
    float4 m = xp[1];
    float4 c = xp[2];

    float w0 = cw[0], w1 = cw[1], w2 = cw[2], b0 = cb[0];

    float o0 = fmaf(a.x, w0, fmaf(a.y, w1, fmaf(a.z, w2, b0)));
    float o1 = fmaf(a.w, w0, fmaf(m.x, w1, fmaf(m.y, w2, b0)));
    float o2 = fmaf(m.z, w0, fmaf(m.w, w1, fmaf(c.x, w2, b0)));
    float o3 = fmaf(c.y, w0, fmaf(c.z, w1, fmaf(c.w, w2, b0)));

    float4 o;
    o.x = fmaxf(o0, 0.0f);
    o.y = fmaxf(o1, 0.0f);
    o.z = fmaxf(o2, 0.0f);
    o.w = fmaxf(o3, 0.0f);
    *reinterpret_cast<float4*>(g_conv + (size_t)b * LP + 4 * i) = o;
}

// ---------------------------------------------------------------------------
// Packed f32x2 + MUFU helpers.
// ---------------------------------------------------------------------------
typedef unsigned long long u64;

__device__ __forceinline__ u64 dup2(float x) {
    u64 r;
    asm("mov.b64 %0, {%1, %1};" : "=l"(r) : "f"(x));
    return r;
}
__device__ __forceinline__ u64 pack2(float lo, float hi) {
    u64 r;
    asm("mov.b64 %0, {%1, %2};" : "=l"(r) : "f"(lo), "f"(hi));
    return r;
}
__device__ __forceinline__ u64 ffma2(u64 a, u64 b, u64 c) {
    u64 d;
    asm("fma.rn.f32x2 %0, %1, %2, %3;" : "=l"(d) : "l"(a), "l"(b), "l"(c));
    return d;
}
__device__ __forceinline__ float hsum2(u64 v) {
    float lo, hi;
    asm("mov.b64 {%0, %1}, %2;" : "=f"(lo), "=f"(hi) : "l"(v));
    return lo + hi;
}
__device__ __forceinline__ float tanh_apx(float x) {
    float y;
    asm("tanh.approx.f32 %0, %1;" : "=f"(y) : "f"(x));
    return y;
}

// Shared-memory broadcast helpers: h vector read back as packed 64-bit pairs.
__device__ __forceinline__ void sts_f32(unsigned addr, float v) {
    asm volatile("st.shared.f32 [%0], %1;" :: "r"(addr), "f"(v) : "memory");
}
__device__ __forceinline__ void lds_v2u64(unsigned addr, u64& a, u64& b) {
    asm volatile("ld.shared.v2.u64 {%0,%1}, [%2];"
                 : "=l"(a), "=l"(b) : "r"(addr) : "memory");
}
__device__ __forceinline__ u64 lds_u64(unsigned addr) {
    u64 a;
    asm volatile("ld.shared.u64 %0, [%1];" : "=l"(a) : "r"(addr) : "memory");
    return a;
}
__device__ __forceinline__ void lds_v2f(unsigned addr, float& a, float& b) {
    asm volatile("ld.shared.v2.f32 {%0,%1}, [%2];"
                 : "=f"(a), "=f"(b) : "r"(addr) : "memory");
}

// ---------------------------------------------------------------------------
// Kernel 2: LSTM scan + final MLP.
// One batch element per 16-lane warp segment; lane j<10 owns hidden unit j.
// Gate dots via FFMA2 packed over k-pairs; h pairs come packed straight from
// smem (no repack on the critical path). c-update algebra restructured to
// drop the sigmoid fix-ups from the tanh->c dependency chain.
// ---------------------------------------------------------------------------
__global__ void __launch_bounds__(128, 1)
lstm_kernel(const float* __restrict__ w_ih,
            const float* __restrict__ w_hh,
            const float* __restrict__ b_ih,
            const float* __restrict__ b_hh,
            const float* __restrict__ mlp_w,
            const float* __restrict__ mlp_b,
            float* __restrict__ out) {
    __shared__ __align__(16) float hbuf[8 * 16];   // 8 segments * 16 slots

    int tid = blockIdx.x * blockDim.x + threadIdx.x;
    int grp = tid >> 4;                 // batch element, 0..511
    int j   = tid & 15;                 // lane within segment
    int jc  = j < HID ? j : HID - 1;    // clamp idle lanes onto valid rows
    if (grp >= BATCH) return;

    int seg = (threadIdx.x >> 4);       // segment within block, 0..7
    unsigned sbase = (unsigned)__cvta_generic_to_shared(&hbuf[seg * 16]);
    unsigned smy   = sbase + 4u * (unsigned)j;

    // Recurrent weights packed over k-pairs (torch gate order i,f,g,o).
    // Sigmoid-gate weights pre-scaled by 0.5 (sigmoid via tanh identity).
    u64 wi2[5], wf2[5], wg2[5], wo2[5];
#pragma unroll
    for (int p = 0; p < 5; p++) {
        wi2[p] = pack2(0.5f * w_hh[(0 * HID + jc) * HID + 2 * p],
                       0.5f * w_hh[(0 * HID + jc) * HID + 2 * p + 1]);
        wf2[p] = pack2(0.5f * w_hh[(1 * HID + jc) * HID + 2 * p],
                       0.5f * w_hh[(1 * HID + jc) * HID + 2 * p + 1]);
        wg2[p] = pack2(       w_hh[(2 * HID + jc) * HID + 2 * p],
                              w_hh[(2 * HID + jc) * HID + 2 * p + 1]);
        wo2[p] = pack2(0.5f * w_hh[(3 * HID + jc) * HID + 2 * p],
                       0.5f * w_hh[(3 * HID + jc) * HID + 2 * p + 1]);
    }
    // Input weight + bias packed into (value, 0): seeded via one FFMA2 each.
    u64 wxi2 = pack2(0.5f * w_ih[0 * HID + jc], 0.0f);
    u64 wxf2 = pack2(0.5f * w_ih[1 * HID + jc], 0.0f);
    u64 wxg2 = pack2(       w_ih[2 * HID + jc], 0.0f);
    u64 wxo2 = pack2(0.5f * w_ih[3 * HID + jc], 0.0f);
    u64 bbi2 = pack2(0.5f * (b_ih[0 * HID + jc] + b_hh[0 * HID + jc]), 0.0f);
    u64 bbf2 = pack2(0.5f * (b_ih[1 * HID + jc] + b_hh[1 * HID + jc]), 0.0f);
    u64 bbg2 = pack2(       (b_ih[2 * HID + jc] + b_hh[2 * HID + jc]), 0.0f);
    u64 bbo2 = pack2(0.5f * (b_ih[3 * HID + jc] + b_hh[3 * HID + jc]), 0.0f);

    float cst = 0.0f;
    float hcst = 0.0f;                  // 0.5 * cst, maintained each step

    // Seed h = 0 in smem.
    sts_f32(smy, 0.0f);

    const float* convp = g_conv + (size_t)grp * LP;
    float4 cur = *reinterpret_cast<const float4*>(convp);

    for (int t4 = 0; t4 < LP / 4; t4++) {
        // Prefetch next quad (padded overread on the last iteration).
        float4 nxt = *reinterpret_cast<const float4*>(convp + 4 * t4 + 4);

        float cts[4] = {cur.x, cur.y, cur.z, cur.w};
#pragma unroll
        for (int u = 0; u < 4; u++) {
            u64 ct2 = dup2(cts[u]);     // off critical path (ct known early)

            // Broadcast previous h as packed pairs (smem broadcast reads).
            u64 h01, h23, h45, h67, h89;
            lds_v2u64(sbase, h01, h23);
            lds_v2u64(sbase + 16u, h45, h67);
            h89 = lds_u64(sbase + 32u);

            // Gate preacts: seed FFMA2 (input+bias in lo half) + 5-pair chain.
            u64 ag2 = ffma2(wxg2, ct2, bbg2);
            u64 ai2 = ffma2(wxi2, ct2, bbi2);
            u64 af2 = ffma2(wxf2, ct2, bbf2);
            u64 ao2 = ffma2(wxo2, ct2, bbo2);

            ag2 = ffma2(wg2[0], h01, ag2);
            ai2 = ffma2(wi2[0], h01, ai2);
            af2 = ffma2(wf2[0], h01, af2);
            ao2 = ffma2(wo2[0], h01, ao2);
            ag2 = ffma2(wg2[1], h23, ag2);
            ai2 = ffma2(wi2[1], h23, ai2);
            af2 = ffma2(wf2[1], h23, af2);
            ao2 = ffma2(wo2[1], h23, ao2);
            ag2 = ffma2(wg2[2], h45, ag2);
            ai2 = ffma2(wi2[2], h45, ai2);
            af2 = ffma2(wf2[2], h45, af2);
            ao2 = ffma2(wo2[2], h45, ao2);
            ag2 = ffma2(wg2[3], h67, ag2);
            ai2 = ffma2(wi2[3], h67, ai2);
            af2 = ffma2(wf2[3], h67, af2);
            ao2 = ffma2(wo2[3], h67, ao2);
            ag2 = ffma2(wg2[4], h89, ag2);
            ai2 = ffma2(wi2[4], h89, ai2);
            af2 = ffma2(wf2[4], h89, af2);
            ao2 = ffma2(wo2[4], h89, ao2);

            float ag = hsum2(ag2);
            float ai = hsum2(ai2);
            float af = hsum2(af2);
            float ao = hsum2(ao2);

            // Activations (MUFU issue order = consumption order).
            float gg = tanh_apx(ag);    // tanh gate
            float ti = tanh_apx(ai);    // tanh(0.5*preact_i)
            float tf = tanh_apx(af);
            float to = tanh_apx(ao);

            // c' = sig(f)*c + sig(i)*g, with sig(x)=0.5*t+0.5 folded:
            //   P = ig*gg = 0.5*gg*ti + 0.5*gg
            //   c' = 0.5*c*tf + (0.5*c + P)
            float hgg = 0.5f * gg;
            float P = fmaf(hgg, ti, hgg);
            float Q = hcst + P;
            cst = fmaf(hcst, tf, Q);
            hcst = 0.5f * cst;

            float og = fmaf(to, 0.5f, 0.5f);
            float h = og * tanh_apx(cst);

            // Publish new h for the next step.
            sts_f32(smy, h);
        }
        cur = nxt;
    }

    // Final MLP: read h_0..h_9 from smem; lanes 0..2 emit the 3 outputs.
    if (j < 3) {
        float h0, h1, h2, h3, h4, h5, h6, h7, h8, h9;
        lds_v2f(sbase,       h0, h1);
        lds_v2f(sbase + 8u,  h2, h3);
        lds_v2f(sbase + 16u, h4, h5);
        lds_v2f(sbase + 24u, h6, h7);
        lds_v2f(sbase + 32u, h8, h9);
        const float* mw = mlp_w + j * HID;
        float acc = mlp_b[j];
        acc = fmaf(mw[0], h0, acc);
        acc = fmaf(mw[1], h1, acc);
        acc = fmaf(mw[2], h2, acc);
        acc = fmaf(mw[3], h3, acc);
        acc = fmaf(mw[4], h4, acc);
        acc = fmaf(mw[5], h5, acc);
        acc = fmaf(mw[6], h6, acc);
        acc = fmaf(mw[7], h7, acc);
        acc = fmaf(mw[8], h8, acc);
        acc = fmaf(mw[9], h9, acc);
        out[grp * 3 + j] = acc;
    }
}

// ---------------------------------------------------------------------------
extern "C" void kernel_launch(void* const* d_in, const int* in_sizes, int n_in,
                              void* d_out, int out_size) {
    const float* x      = (const float*)d_in[0];
    const float* conv_w = (const float*)d_in[1];
    const float* conv_b = (const float*)d_in[2];
    const float* w_ih   = (const float*)d_in[3];
    const float* w_hh   = (const float*)d_in[4];
    const float* b_ih   = (const float*)d_in[5];
    const float* b_hh   = (const float*)d_in[6];
    const float* mlp_w  = (const float*)d_in[7];
    const float* mlp_b  = (const float*)d_in[8];
    float* out = (float*)d_out;

    // Conv: 512*2048 threads, 4 outputs each.
    {
        int total = BATCH * (LP / 4);
        int threads = 256;
        int blocks = (total + threads - 1) / threads;
        conv_kernel<<<blocks, threads>>>(x, conv_w, conv_b);
    }
    // LSTM: 512 groups * 16 lanes = 8192 threads (64 blocks x 128).
    {
        int threads = 128;
        int blocks = (BATCH * 16) / threads;   // 64
        lstm_kernel<<<blocks, threads>>>(w_ih, w_hh, b_ih, b_hh, mlp_w, mlp_b, out);
    }
}